// round 1
// baseline (speedup 1.0000x reference)
#include <cuda_runtime.h>
#include <math.h>

// Depth2normal: per-pixel 3x3 plane fit via smallest eigenvector of 4x4 AtA.
// One thread per pixel; fully-unrolled register-resident 4x4 Jacobi eigensolver.

#define KH 480
#define KW 640

__global__ __launch_bounds__(256)
void d2n_kernel(const float* __restrict__ pts, float* __restrict__ out,
                int B, int H, int W) {
    int idx = blockIdx.x * blockDim.x + threadIdx.x;
    int total = B * H * W;
    if (idx >= total) return;

    int x = idx % W;
    int y = (idx / W) % H;
    int b = idx / (W * H);

    size_t HW = (size_t)H * W;
    const float* base = pts + (size_t)b * 3 * HW;
    const float* px = base;
    const float* py = base + HW;
    const float* pz = base + 2 * HW;

    // ---- Build AtA (4x4 symmetric) from valid neighbors ----
    float m00 = 0.f, m01 = 0.f, m02 = 0.f, m03 = 0.f;
    float m11 = 0.f, m12 = 0.f, m13 = 0.f;
    float m22 = 0.f, m23 = 0.f;
    int cnt = 0;
    float cx = 0.f, cy = 0.f, cz = 0.f;
    bool centerValid = false;

    #pragma unroll
    for (int dy = -1; dy <= 1; ++dy) {
        #pragma unroll
        for (int dx = -1; dx <= 1; ++dx) {
            int yy = y + dy, xx = x + dx;
            bool in = (yy >= 0) && (yy < H) && (xx >= 0) && (xx < W);
            float X = 0.f, Y = 0.f, Z = 0.f;
            if (in) {
                size_t off = (size_t)yy * W + xx;
                X = __ldg(px + off);
                Y = __ldg(py + off);
                Z = __ldg(pz + off);
            }
            bool v = in && (Z > 0.0f) && (Z < 10.0f);
            if (dy == 0 && dx == 0) {
                cx = X; cy = Y; cz = Z;
                centerValid = v;
            }
            if (v) {
                cnt++;
                m00 = fmaf(X, X, m00);
                m01 = fmaf(X, Y, m01);
                m02 = fmaf(X, Z, m02);
                m03 += X;
                m11 = fmaf(Y, Y, m11);
                m12 = fmaf(Y, Z, m12);
                m13 += Y;
                m22 = fmaf(Z, Z, m22);
                m23 += Z;
            }
        }
    }
    float m33 = (float)cnt;

    // ---- Jacobi eigensolver on 4x4 symmetric matrix (registers only) ----
    float a[4][4];
    a[0][0] = m00; a[0][1] = m01; a[0][2] = m02; a[0][3] = m03;
    a[1][0] = m01; a[1][1] = m11; a[1][2] = m12; a[1][3] = m13;
    a[2][0] = m02; a[2][1] = m12; a[2][2] = m22; a[2][3] = m23;
    a[3][0] = m03; a[3][1] = m13; a[3][2] = m23; a[3][3] = m33;

    float vv[4][4];
    #pragma unroll
    for (int i = 0; i < 4; ++i)
        #pragma unroll
        for (int j = 0; j < 4; ++j)
            vv[i][j] = (i == j) ? 1.0f : 0.0f;

    const int PP[6] = {0, 0, 0, 1, 1, 2};
    const int QQ[6] = {1, 2, 3, 2, 3, 3};

    #pragma unroll
    for (int sweep = 0; sweep < 6; ++sweep) {
        #pragma unroll
        for (int pi = 0; pi < 6; ++pi) {
            const int p = PP[pi];
            const int q = QQ[pi];
            float apq = a[p][q];
            float scale = fabsf(a[p][p]) + fabsf(a[q][q]);
            if (fabsf(apq) > 1e-12f * scale + 1e-30f) {
                float theta = (a[q][q] - a[p][p]) / (2.0f * apq);
                float t = 1.0f / (fabsf(theta) + sqrtf(fmaf(theta, theta, 1.0f)));
                t = copysignf(t, theta);
                float c = rsqrtf(fmaf(t, t, 1.0f));
                float s = t * c;
                // A <- A * G   (columns p, q)
                #pragma unroll
                for (int k = 0; k < 4; ++k) {
                    float akp = a[k][p], akq = a[k][q];
                    a[k][p] = akp * c - akq * s;
                    a[k][q] = akp * s + akq * c;
                }
                // A <- G^T * A (rows p, q)
                #pragma unroll
                for (int k = 0; k < 4; ++k) {
                    float apk = a[p][k], aqk = a[q][k];
                    a[p][k] = apk * c - aqk * s;
                    a[q][k] = apk * s + aqk * c;
                }
                // V <- V * G
                #pragma unroll
                for (int k = 0; k < 4; ++k) {
                    float vkp = vv[k][p], vkq = vv[k][q];
                    vv[k][p] = vkp * c - vkq * s;
                    vv[k][q] = vkp * s + vkq * c;
                }
            }
        }
    }

    // ---- Pick eigenvector of the smallest eigenvalue ----
    int jmin = 0;
    float emin = a[0][0];
    #pragma unroll
    for (int j = 1; j < 4; ++j) {
        if (a[j][j] < emin) { emin = a[j][j]; jmin = j; }
    }
    float nx = 0.f, ny = 0.f, nz = 0.f;
    #pragma unroll
    for (int j = 0; j < 4; ++j) {
        if (j == jmin) { nx = vv[0][j]; ny = vv[1][j]; nz = vv[2][j]; }
    }

    // ---- Normalize (first 3 components), flip, mask ----
    float nrm = sqrtf(fmaf(nx, nx, fmaf(ny, ny, nz * nz)));
    float inv = 1.0f / fmaxf(nrm, 1e-12f);
    nx *= inv; ny *= inv; nz *= inv;

    float dot = fmaf(nx, cx, fmaf(ny, cy, nz * cz));
    float flip = (dot > 0.0f) ? 1.0f : ((dot < 0.0f) ? -1.0f : 0.0f);
    nx *= flip; ny *= flip; nz *= flip;

    float finalNorm = sqrtf(fmaf(nx, nx, fmaf(ny, ny, nz * nz)));
    bool mask = centerValid && (cnt >= 4) && (finalNorm > 0.5f);

    // ---- Write outputs: normal (B,3,H,W) then mask (B,1,H,W) as 0/1 float ----
    size_t pix = (size_t)y * W + x;
    out[((size_t)b * 3 + 0) * HW + pix] = nx;
    out[((size_t)b * 3 + 1) * HW + pix] = ny;
    out[((size_t)b * 3 + 2) * HW + pix] = nz;
    out[(size_t)B * 3 * HW + (size_t)b * HW + pix] = mask ? 1.0f : 0.0f;
}

extern "C" void kernel_launch(void* const* d_in, const int* in_sizes, int n_in,
                              void* d_out, int out_size) {
    const float* pts = (const float*)d_in[0];
    float* out = (float*)d_out;
    int H = KH, W = KW;
    int B = in_sizes[0] / (3 * H * W);
    int total = B * H * W;
    int threads = 256;
    int blocks = (total + threads - 1) / threads;
    d2n_kernel<<<blocks, threads>>>(pts, out, B, H, W);
}

// round 2
// speedup vs baseline: 1.5923x; 1.5923x over previous
#include <cuda_runtime.h>
#include <math.h>

// Depth2normal: per-pixel 3x3 plane fit via smallest eigenvector of 4x4 AtA.
// One thread per pixel; symmetric-update Jacobi (4 sweeps), approx MUFU math,
// 3x4 eigenvector accumulation, interior fast path.

#define KH 480
#define KW 640

__device__ __forceinline__ float sqrt_approx(float x) {
    float r; asm("sqrt.approx.f32 %0, %1;" : "=f"(r) : "f"(x)); return r;
}
__device__ __forceinline__ float rsqrt_approx(float x) {
    float r; asm("rsqrt.approx.f32 %0, %1;" : "=f"(r) : "f"(x)); return r;
}

// One Jacobi rotation on pair (p,q) of symmetric 4x4 A with 3x4 eigvec rows.
// APP/AQQ/APQ: diagonal + pivot. (AK1P,AK1Q),(AK2P,AK2Q): the two off-pair
// symmetric elements. (VPr,VQr): columns p,q of eigenvector row r (r=0..2).
#define JROT(APP, AQQ, APQ, AK1P, AK1Q, AK2P, AK2Q, VP0, VQ0, VP1, VQ1, VP2, VQ2) do { \
    float apq_ = (APQ);                                                     \
    float th_  = __fdividef((AQQ) - (APP), 2.0f * apq_);                    \
    float t_   = __fdividef(1.0f, fabsf(th_) + sqrt_approx(fmaf(th_, th_, 1.0f))); \
    t_ = copysignf(t_, th_);                                                \
    t_ = (fabsf(apq_) < 1e-30f) ? 0.0f : t_;                                \
    float c_ = rsqrt_approx(fmaf(t_, t_, 1.0f));                            \
    float s_ = t_ * c_;                                                     \
    (APP) = fmaf(-t_, apq_, (APP));                                         \
    (AQQ) = fmaf( t_, apq_, (AQQ));                                         \
    (APQ) = 0.0f;                                                           \
    { float u_ = (AK1P), w_ = (AK1Q);                                       \
      (AK1P) = fmaf(c_, u_, -s_ * w_); (AK1Q) = fmaf(s_, u_, c_ * w_); }    \
    { float u_ = (AK2P), w_ = (AK2Q);                                       \
      (AK2P) = fmaf(c_, u_, -s_ * w_); (AK2Q) = fmaf(s_, u_, c_ * w_); }    \
    { float u_ = (VP0), w_ = (VQ0);                                         \
      (VP0) = fmaf(c_, u_, -s_ * w_); (VQ0) = fmaf(s_, u_, c_ * w_); }      \
    { float u_ = (VP1), w_ = (VQ1);                                         \
      (VP1) = fmaf(c_, u_, -s_ * w_); (VQ1) = fmaf(s_, u_, c_ * w_); }      \
    { float u_ = (VP2), w_ = (VQ2);                                         \
      (VP2) = fmaf(c_, u_, -s_ * w_); (VQ2) = fmaf(s_, u_, c_ * w_); }      \
} while (0)

// Accumulate one (possibly invalid) neighbor into AtA. Invalid => weight 0.
#define ACCUM(X, Y, Z) do {                                                 \
    float w_  = ((Z) > 0.0f && (Z) < 10.0f) ? 1.0f : 0.0f;                  \
    float xm_ = (X) * w_, ym_ = (Y) * w_, zm_ = (Z) * w_;                   \
    a00 = fmaf(xm_, (X), a00); a01 = fmaf(xm_, (Y), a01);                   \
    a02 = fmaf(xm_, (Z), a02); a03 += xm_;                                  \
    a11 = fmaf(ym_, (Y), a11); a12 = fmaf(ym_, (Z), a12); a13 += ym_;       \
    a22 = fmaf(zm_, (Z), a22); a23 += zm_;                                  \
    a33 += w_;                                                              \
} while (0)

__global__ __launch_bounds__(256)
void d2n_kernel(const float* __restrict__ pts, float* __restrict__ out, int B) {
    const int HW = KH * KW;
    int idx = blockIdx.x * blockDim.x + threadIdx.x;
    if (idx >= B * HW) return;

    int x = idx % KW;
    int y = (idx / KW) % KH;
    int b = idx / HW;

    const float* px = pts + b * 3 * HW;
    const float* py = px + HW;
    const float* pz = py + HW;
    int off = y * KW + x;

    float a00 = 0.f, a01 = 0.f, a02 = 0.f, a03 = 0.f;
    float a11 = 0.f, a12 = 0.f, a13 = 0.f;
    float a22 = 0.f, a23 = 0.f, a33 = 0.f;
    float cx, cy, cz;

    bool interior = ((unsigned)(x - 1) < (unsigned)(KW - 2)) &&
                    ((unsigned)(y - 1) < (unsigned)(KH - 2));
    if (interior) {
        #pragma unroll
        for (int dy = -1; dy <= 1; ++dy) {
            #pragma unroll
            for (int dx = -1; dx <= 1; ++dx) {
                int o = off + dy * KW + dx;
                float X = __ldg(px + o);
                float Y = __ldg(py + o);
                float Z = __ldg(pz + o);
                if (dy == 0 && dx == 0) { cx = X; cy = Y; cz = Z; }
                ACCUM(X, Y, Z);
            }
        }
    } else {
        #pragma unroll
        for (int dy = -1; dy <= 1; ++dy) {
            #pragma unroll
            for (int dx = -1; dx <= 1; ++dx) {
                int yy = y + dy, xx = x + dx;
                bool in = ((unsigned)yy < (unsigned)KH) && ((unsigned)xx < (unsigned)KW);
                float X = 0.f, Y = 0.f, Z = -1.f;  // Z=-1 => invalid
                if (in) {
                    int o = yy * KW + xx;
                    X = __ldg(px + o);
                    Y = __ldg(py + o);
                    Z = __ldg(pz + o);
                }
                if (dy == 0 && dx == 0) { cx = X; cy = Y; cz = Z; }
                ACCUM(X, Y, Z);
            }
        }
    }

    float cnt = a33;  // save before rotations mutate a33
    bool centerValid = (cz > 0.0f) && (cz < 10.0f);

    // Eigenvector rows 0..2, columns 0..3 (V starts as identity).
    float v00 = 1.f, v01 = 0.f, v02 = 0.f, v03 = 0.f;
    float v10 = 0.f, v11 = 1.f, v12 = 0.f, v13 = 0.f;
    float v20 = 0.f, v21 = 0.f, v22 = 1.f, v23 = 0.f;

    #pragma unroll
    for (int sweep = 0; sweep < 4; ++sweep) {
        JROT(a00, a11, a01, a02, a12, a03, a13, v00, v01, v10, v11, v20, v21);
        JROT(a00, a22, a02, a01, a12, a03, a23, v00, v02, v10, v12, v20, v22);
        JROT(a00, a33, a03, a01, a13, a02, a23, v00, v03, v10, v13, v20, v23);
        JROT(a11, a22, a12, a01, a02, a13, a23, v01, v02, v11, v12, v21, v22);
        JROT(a11, a33, a13, a01, a03, a12, a23, v01, v03, v11, v13, v21, v23);
        JROT(a22, a33, a23, a02, a03, a12, a13, v02, v03, v12, v13, v22, v23);
    }

    // Pick eigenvector of smallest eigenvalue (branchless selects).
    float e = a00, nx = v00, ny = v10, nz = v20;
    if (a11 < e) { e = a11; nx = v01; ny = v11; nz = v21; }
    if (a22 < e) { e = a22; nx = v02; ny = v12; nz = v22; }
    if (a33 < e) { e = a33; nx = v03; ny = v13; nz = v23; }

    // Normalize, sign-flip toward the center point, mask.
    float n2  = fmaf(nx, nx, fmaf(ny, ny, nz * nz));
    float inv = rsqrt_approx(fmaxf(n2, 1e-24f));
    nx *= inv; ny *= inv; nz *= inv;

    float dot  = fmaf(nx, cx, fmaf(ny, cy, nz * cz));
    float flip = (dot > 0.0f) ? 1.0f : ((dot < 0.0f) ? -1.0f : 0.0f);
    nx *= flip; ny *= flip; nz *= flip;

    float fn2 = fmaf(nx, nx, fmaf(ny, ny, nz * nz));
    bool mask = centerValid && (cnt >= 4.0f) && (fn2 > 0.25f);

    out[(b * 3 + 0) * HW + off] = nx;
    out[(b * 3 + 1) * HW + off] = ny;
    out[(b * 3 + 2) * HW + off] = nz;
    out[(B * 3 + b) * HW + off] = mask ? 1.0f : 0.0f;
}

extern "C" void kernel_launch(void* const* d_in, const int* in_sizes, int n_in,
                              void* d_out, int out_size) {
    const float* pts = (const float*)d_in[0];
    float* out = (float*)d_out;
    int B = in_sizes[0] / (3 * KH * KW);
    int total = B * KH * KW;
    int threads = 256;
    int blocks = (total + threads - 1) / threads;
    d2n_kernel<<<blocks, threads>>>(pts, out, B);
}

// round 4
// speedup vs baseline: 2.7393x; 1.7204x over previous
#include <cuda_runtime.h>
#include <math.h>

// Depth2normal: per-pixel 3x3 plane fit via smallest eigenvector of 4x4 AtA.
// One thread per pixel; symmetric-update Jacobi (4 sweeps), 1-division rotation,
// approx MUFU math, 3x4 eigenvector accumulation, interior fast path.
// 3-D grid: no div/mod index decomposition, no tail guard.

#define KH 480
#define KW 640
#define BX 128

__device__ __forceinline__ float sqrt_approx(float x) {
    float r; asm("sqrt.approx.f32 %0, %1;" : "=f"(r) : "f"(x)); return r;
}
__device__ __forceinline__ float rsqrt_approx(float x) {
    float r; asm("rsqrt.approx.f32 %0, %1;" : "=f"(r) : "f"(x)); return r;
}

// One Jacobi rotation on pair (p,q) of symmetric 4x4 A with 3x4 eigvec rows.
// t = apq / (d + copysign(sqrt(d^2+apq^2), d)),  d = (aqq-app)/2
// (algebraically identical to the classic theta-form, one division only).
#define JROT(APP, AQQ, APQ, AK1P, AK1Q, AK2P, AK2Q, VP0, VQ0, VP1, VQ1, VP2, VQ2) do { \
    float apq_ = (APQ);                                                     \
    float d_   = 0.5f * ((AQQ) - (APP));                                    \
    float r_   = sqrt_approx(fmaf(d_, d_, apq_ * apq_));                    \
    float den_ = d_ + copysignf(r_, d_);                                    \
    float t_   = __fdividef(apq_, den_);                                    \
    t_ = (fabsf(apq_) < 1e-30f) ? 0.0f : t_;                                \
    float c_ = rsqrt_approx(fmaf(t_, t_, 1.0f));                            \
    float s_ = t_ * c_;                                                     \
    (APP) = fmaf(-t_, apq_, (APP));                                         \
    (AQQ) = fmaf( t_, apq_, (AQQ));                                         \
    (APQ) = 0.0f;                                                           \
    { float u_ = (AK1P), w_ = (AK1Q);                                       \
      (AK1P) = fmaf(c_, u_, -s_ * w_); (AK1Q) = fmaf(s_, u_, c_ * w_); }    \
    { float u_ = (AK2P), w_ = (AK2Q);                                       \
      (AK2P) = fmaf(c_, u_, -s_ * w_); (AK2Q) = fmaf(s_, u_, c_ * w_); }    \
    { float u_ = (VP0), w_ = (VQ0);                                         \
      (VP0) = fmaf(c_, u_, -s_ * w_); (VQ0) = fmaf(s_, u_, c_ * w_); }      \
    { float u_ = (VP1), w_ = (VQ1);                                         \
      (VP1) = fmaf(c_, u_, -s_ * w_); (VQ1) = fmaf(s_, u_, c_ * w_); }      \
    { float u_ = (VP2), w_ = (VQ2);                                         \
      (VP2) = fmaf(c_, u_, -s_ * w_); (VQ2) = fmaf(s_, u_, c_ * w_); }      \
} while (0)

// Accumulate one (possibly invalid) neighbor into AtA. Invalid => weight 0.
#define ACCUM(X, Y, Z) do {                                                 \
    float w_  = ((Z) > 0.0f && (Z) < 10.0f) ? 1.0f : 0.0f;                  \
    float xm_ = (X) * w_, ym_ = (Y) * w_, zm_ = (Z) * w_;                   \
    a00 = fmaf(xm_, (X), a00); a01 = fmaf(xm_, (Y), a01);                   \
    a02 = fmaf(xm_, (Z), a02); a03 += xm_;                                  \
    a11 = fmaf(ym_, (Y), a11); a12 = fmaf(ym_, (Z), a12); a13 += ym_;       \
    a22 = fmaf(zm_, (Z), a22); a23 += zm_;                                  \
    a33 += w_;                                                              \
} while (0)

__global__ __launch_bounds__(BX)
void d2n_kernel(const float* __restrict__ pts, float* __restrict__ out, int B) {
    const int HW = KH * KW;
    int x = blockIdx.x * BX + threadIdx.x;
    int y = blockIdx.y;
    int b = blockIdx.z;

    const float* px = pts + b * 3 * HW;
    const float* py = px + HW;
    const float* pz = py + HW;
    int off = y * KW + x;

    float a00 = 0.f, a01 = 0.f, a02 = 0.f, a03 = 0.f;
    float a11 = 0.f, a12 = 0.f, a13 = 0.f;
    float a22 = 0.f, a23 = 0.f, a33 = 0.f;
    float cx, cy, cz;

    bool interior = ((unsigned)(x - 1) < (unsigned)(KW - 2)) &&
                    ((unsigned)(y - 1) < (unsigned)(KH - 2));
    if (interior) {
        #pragma unroll
        for (int dy = -1; dy <= 1; ++dy) {
            #pragma unroll
            for (int dx = -1; dx <= 1; ++dx) {
                int o = off + dy * KW + dx;
                float X = __ldg(px + o);
                float Y = __ldg(py + o);
                float Z = __ldg(pz + o);
                if (dy == 0 && dx == 0) { cx = X; cy = Y; cz = Z; }
                ACCUM(X, Y, Z);
            }
        }
    } else {
        #pragma unroll
        for (int dy = -1; dy <= 1; ++dy) {
            #pragma unroll
            for (int dx = -1; dx <= 1; ++dx) {
                int yy = y + dy, xx = x + dx;
                bool in = ((unsigned)yy < (unsigned)KH) && ((unsigned)xx < (unsigned)KW);
                float X = 0.f, Y = 0.f, Z = -1.f;  // Z=-1 => invalid
                if (in) {
                    int o = yy * KW + xx;
                    X = __ldg(px + o);
                    Y = __ldg(py + o);
                    Z = __ldg(pz + o);
                }
                if (dy == 0 && dx == 0) { cx = X; cy = Y; cz = Z; }
                ACCUM(X, Y, Z);
            }
        }
    }

    float cnt = a33;  // save before rotations mutate a33
    bool centerValid = (cz > 0.0f) && (cz < 10.0f);

    // Eigenvector rows 0..2, columns 0..3 (V starts as identity).
    float v00 = 1.f, v01 = 0.f, v02 = 0.f, v03 = 0.f;
    float v10 = 0.f, v11 = 1.f, v12 = 0.f, v13 = 0.f;
    float v20 = 0.f, v21 = 0.f, v22 = 1.f, v23 = 0.f;

    #pragma unroll
    for (int sweep = 0; sweep < 4; ++sweep) {
        JROT(a00, a11, a01, a02, a12, a03, a13, v00, v01, v10, v11, v20, v21);
        JROT(a00, a22, a02, a01, a12, a03, a23, v00, v02, v10, v12, v20, v22);
        JROT(a00, a33, a03, a01, a13, a02, a23, v00, v03, v10, v13, v20, v23);
        JROT(a11, a22, a12, a01, a02, a13, a23, v01, v02, v11, v12, v21, v22);
        JROT(a11, a33, a13, a01, a03, a12, a23, v01, v03, v11, v13, v21, v23);
        JROT(a22, a33, a23, a02, a03, a12, a13, v02, v03, v12, v13, v22, v23);
    }

    // Pick eigenvector of smallest eigenvalue (branchless selects).
    float e = a00, nx = v00, ny = v10, nz = v20;
    if (a11 < e) { e = a11; nx = v01; ny = v11; nz = v21; }
    if (a22 < e) { e = a22; nx = v02; ny = v12; nz = v22; }
    if (a33 < e) { e = a33; nx = v03; ny = v13; nz = v23; }

    // Sign from unnormalized dot (positive scaling preserves sign), then
    // normalize and flip in one scale each.
    float n2  = fmaf(nx, nx, fmaf(ny, ny, nz * nz));
    float inv = rsqrt_approx(fmaxf(n2, 1e-24f));
    float dot = fmaf(nx, cx, fmaf(ny, cy, nz * cz));
    float flip = (dot > 0.0f) ? 1.0f : ((dot < 0.0f) ? -1.0f : 0.0f);
    float sgn = inv * flip;
    nx *= sgn; ny *= sgn; nz *= sgn;

    float fn2 = fmaf(nx, nx, fmaf(ny, ny, nz * nz));
    bool mask = centerValid && (cnt >= 4.0f) && (fn2 > 0.25f);

    out[(b * 3 + 0) * HW + off] = nx;
    out[(b * 3 + 1) * HW + off] = ny;
    out[(b * 3 + 2) * HW + off] = nz;
    out[(B * 3 + b) * HW + off] = mask ? 1.0f : 0.0f;
}

extern "C" void kernel_launch(void* const* d_in, const int* in_sizes, int n_in,
                              void* d_out, int out_size) {
    const float* pts = (const float*)d_in[0];
    float* out = (float*)d_out;
    int B = in_sizes[0] / (3 * KH * KW);
    dim3 block(BX, 1, 1);
    dim3 grid(KW / BX, KH, B);
    d2n_kernel<<<grid, block>>>(pts, out, B);
}

// round 6
// speedup vs baseline: 2.8473x; 1.0394x over previous
#include <cuda_runtime.h>
#include <math.h>

// Depth2normal: per-pixel 3x3 plane fit via smallest eigenvector of 4x4 AtA.
// Two pixels per thread, packed f32x2 (FFMA2) math throughout the FMA-heavy
// phases; scalar MUFU angle chain per lane. 4-sweep symmetric-update Jacobi
// with predecessor-zero rotation specializations.

#define KH 480
#define KW 640
#define BX 64

typedef unsigned long long u64;

__device__ __forceinline__ float sqrt_approx(float x) {
    float r; asm("sqrt.approx.f32 %0, %1;" : "=f"(r) : "f"(x)); return r;
}
__device__ __forceinline__ float rsqrt_approx(float x) {
    float r; asm("rsqrt.approx.f32 %0, %1;" : "=f"(r) : "f"(x)); return r;
}
__device__ __forceinline__ u64 pk2(float a, float b) {
    u64 r; asm("mov.b64 %0, {%1, %2};" : "=l"(r) : "f"(a), "f"(b)); return r;
}
__device__ __forceinline__ void upk(u64 v, float& a, float& b) {
    asm("mov.b64 {%0, %1}, %2;" : "=f"(a), "=f"(b) : "l"(v));
}
__device__ __forceinline__ u64 f2mul(u64 a, u64 b) {
    u64 r; asm("mul.rn.f32x2 %0, %1, %2;" : "=l"(r) : "l"(a), "l"(b)); return r;
}
__device__ __forceinline__ u64 f2add(u64 a, u64 b) {
    u64 r; asm("add.rn.f32x2 %0, %1, %2;" : "=l"(r) : "l"(a), "l"(b)); return r;
}
__device__ __forceinline__ u64 f2fma(u64 a, u64 b, u64 c) {
    u64 r; asm("fma.rn.f32x2 %0, %1, %2, %3;" : "=l"(r) : "l"(a), "l"(b), "l"(c)); return r;
}

// One packed Jacobi rotation (both pixels at once).
// ZMODE: 0 none; 1 K1P==0; 2 K2P==0; 3 K2Q==0; 4 K1Q==0 && K2P==0.
// Zeros are exact (the predecessor rotation assigned APQ = 0).
template <int ZMODE>
__device__ __forceinline__ void jrot2(
    u64& APP, u64& AQQ, u64& APQ,
    u64& K1P, u64& K1Q, u64& K2P, u64& K2Q,
    u64& V0P, u64& V0Q, u64& V1P, u64& V1Q, u64& V2P, u64& V2Q,
    u64 KHALF, u64 KNEGHALF, u64 KNEG1)
{
    u64 DIF = f2fma(KHALF, AQQ, f2mul(KNEGHALF, APP));   // d = (aqq-app)/2
    u64 R2  = f2fma(DIF, DIF, f2mul(APQ, APQ));          // d^2 + apq^2
    float dA, dB, r2A, r2B, aA, aB;
    upk(DIF, dA, dB); upk(R2, r2A, r2B); upk(APQ, aA, aB);
    float denA = dA + copysignf(sqrt_approx(r2A), dA);
    float denB = dB + copysignf(sqrt_approx(r2B), dB);
    float tA = __fdividef(aA, denA);
    float tB = __fdividef(aB, denB);
    tA = (fabsf(denA) < 1e-35f) ? 0.0f : tA;
    tB = (fabsf(denB) < 1e-35f) ? 0.0f : tB;
    float cA = rsqrt_approx(fmaf(tA, tA, 1.0f));
    float cB = rsqrt_approx(fmaf(tB, tB, 1.0f));
    u64 T = pk2(tA, tB);
    u64 C = pk2(cA, cB);
    u64 S  = f2mul(T, C);
    u64 NS = f2mul(KNEG1, S);
    u64 NAPQ = f2mul(KNEG1, APQ);
    APP = f2fma(T, NAPQ, APP);
    AQQ = f2fma(T, APQ, AQQ);
    APQ = 0ull;
    // K1 pair
    if (ZMODE == 1) {                // K1P == 0
        K1P = f2mul(NS, K1Q);
        K1Q = f2mul(C, K1Q);
    } else if (ZMODE == 4) {         // K1Q == 0
        u64 p = K1P;
        K1P = f2mul(C, p);
        K1Q = f2mul(S, p);
    } else {
        u64 p = K1P, q = K1Q;
        K1P = f2fma(C, p, f2mul(NS, q));
        K1Q = f2fma(S, p, f2mul(C, q));
    }
    // K2 pair
    if (ZMODE == 2 || ZMODE == 4) {  // K2P == 0
        K2P = f2mul(NS, K2Q);
        K2Q = f2mul(C, K2Q);
    } else if (ZMODE == 3) {         // K2Q == 0
        u64 p = K2P;
        K2P = f2mul(C, p);
        K2Q = f2mul(S, p);
    } else {
        u64 p = K2P, q = K2Q;
        K2P = f2fma(C, p, f2mul(NS, q));
        K2Q = f2fma(S, p, f2mul(C, q));
    }
    // V rows
    { u64 p = V0P, q = V0Q; V0P = f2fma(C, p, f2mul(NS, q)); V0Q = f2fma(S, p, f2mul(C, q)); }
    { u64 p = V1P, q = V1Q; V1P = f2fma(C, p, f2mul(NS, q)); V1Q = f2fma(S, p, f2mul(C, q)); }
    { u64 p = V2P, q = V2Q; V2P = f2fma(C, p, f2mul(NS, q)); V2Q = f2fma(S, p, f2mul(C, q)); }
}

__global__ __launch_bounds__(BX, 12)
void d2n_kernel(const float* __restrict__ pts, float* __restrict__ out, int B) {
    const int HW = KH * KW;
    int x0 = (blockIdx.x * BX + threadIdx.x) * 2;   // even, lane A; lane B = x0+1
    int y = blockIdx.y;
    int b = blockIdx.z;

    const float* px = pts + b * 3 * HW;
    const float* py = px + HW;
    const float* pz = py + HW;
    int off = y * KW + x0;

    // ---- Load 3 rows x 4 cols x 3 planes (shared stencil for the pair) ----
    float Xv[3][4], Yv[3][4], Zv[3][4];
    bool interior = (y >= 1) && (y < KH - 1) && (x0 >= 1) && (x0 <= KW - 3);
    if (interior) {
        #pragma unroll
        for (int r = 0; r < 3; ++r)
            #pragma unroll
            for (int c = 0; c < 4; ++c) {
                int o = off + (r - 1) * KW + (c - 1);
                Xv[r][c] = __ldg(px + o);
                Yv[r][c] = __ldg(py + o);
                Zv[r][c] = __ldg(pz + o);
            }
    } else {
        #pragma unroll
        for (int r = 0; r < 3; ++r)
            #pragma unroll
            for (int c = 0; c < 4; ++c) {
                int yy = y + r - 1, xx = x0 + c - 1;
                bool in = ((unsigned)yy < (unsigned)KH) && ((unsigned)xx < (unsigned)KW);
                float X = 0.f, Y = 0.f, Z = -1.f;   // Z=-1 => invalid
                if (in) {
                    int o = yy * KW + xx;
                    X = __ldg(px + o); Y = __ldg(py + o); Z = __ldg(pz + o);
                }
                Xv[r][c] = X; Yv[r][c] = Y; Zv[r][c] = Z;
            }
    }

    // ---- Packed AtA accumulation (9 stencil positions, both pixels) ----
    u64 A00 = 0, A01 = 0, A02 = 0, A03 = 0;
    u64 A11 = 0, A12 = 0, A13 = 0;
    u64 A22 = 0, A23 = 0, A33 = 0;
    #pragma unroll
    for (int r = 0; r < 3; ++r)
        #pragma unroll
        for (int j = 0; j < 3; ++j) {
            float za = Zv[r][j], zb = Zv[r][j + 1];
            float wa = (fabsf(za - 5.0f) < 5.0f) ? 1.0f : 0.0f;  // 0<z<10
            float wb = (fabsf(zb - 5.0f) < 5.0f) ? 1.0f : 0.0f;
            u64 PX = pk2(Xv[r][j], Xv[r][j + 1]);
            u64 PY = pk2(Yv[r][j], Yv[r][j + 1]);
            u64 PZ = pk2(za, zb);
            u64 W  = pk2(wa, wb);
            u64 XM = f2mul(PX, W), YM = f2mul(PY, W), ZM = f2mul(PZ, W);
            A00 = f2fma(XM, PX, A00); A01 = f2fma(XM, PY, A01);
            A02 = f2fma(XM, PZ, A02); A03 = f2add(A03, XM);
            A11 = f2fma(YM, PY, A11); A12 = f2fma(YM, PZ, A12);
            A13 = f2add(A13, YM);
            A22 = f2fma(ZM, PZ, A22); A23 = f2add(A23, ZM);
            A33 = f2add(A33, W);
        }

    float cxA = Xv[1][1], cyA = Yv[1][1], czA = Zv[1][1];
    float cxB = Xv[1][2], cyB = Yv[1][2], czB = Zv[1][2];
    u64 CNT = A33;   // save before rotations mutate A33

    const u64 KHALF = pk2(0.5f, 0.5f);
    const u64 KNEGHALF = pk2(-0.5f, -0.5f);
    const u64 KNEG1 = pk2(-1.0f, -1.0f);

    // Eigenvector rows 0..2, columns 0..3 (identity), packed.
    u64 v00 = pk2(1.f, 1.f), v01 = 0, v02 = 0, v03 = 0;
    u64 v10 = 0, v11 = pk2(1.f, 1.f), v12 = 0, v13 = 0;
    u64 v20 = 0, v21 = 0, v22 = pk2(1.f, 1.f), v23 = 0;

    #pragma unroll
    for (int s = 0; s < 4; ++s) {
        jrot2<0>(A00, A11, A01, A02, A12, A03, A13, v00, v01, v10, v11, v20, v21, KHALF, KNEGHALF, KNEG1);
        jrot2<1>(A00, A22, A02, A01, A12, A03, A23, v00, v02, v10, v12, v20, v22, KHALF, KNEGHALF, KNEG1); // a01==0
        jrot2<2>(A00, A33, A03, A01, A13, A02, A23, v00, v03, v10, v13, v20, v23, KHALF, KNEGHALF, KNEG1); // a02==0
        jrot2<0>(A11, A22, A12, A01, A02, A13, A23, v01, v02, v11, v12, v21, v22, KHALF, KNEGHALF, KNEG1);
        jrot2<4>(A11, A33, A13, A01, A03, A12, A23, v01, v03, v11, v13, v21, v23, KHALF, KNEGHALF, KNEG1); // a03==0, a12==0
        jrot2<3>(A22, A33, A23, A02, A03, A12, A13, v02, v03, v12, v13, v22, v23, KHALF, KNEGHALF, KNEG1); // a13==0
    }

    // ---- Per-lane epilogue ----
    float dg[2][4];
    upk(A00, dg[0][0], dg[1][0]); upk(A11, dg[0][1], dg[1][1]);
    upk(A22, dg[0][2], dg[1][2]); upk(A33, dg[0][3], dg[1][3]);
    float V[3][4][2];
    upk(v00, V[0][0][0], V[0][0][1]); upk(v01, V[0][1][0], V[0][1][1]);
    upk(v02, V[0][2][0], V[0][2][1]); upk(v03, V[0][3][0], V[0][3][1]);
    upk(v10, V[1][0][0], V[1][0][1]); upk(v11, V[1][1][0], V[1][1][1]);
    upk(v12, V[1][2][0], V[1][2][1]); upk(v13, V[1][3][0], V[1][3][1]);
    upk(v20, V[2][0][0], V[2][0][1]); upk(v21, V[2][1][0], V[2][1][1]);
    upk(v22, V[2][2][0], V[2][2][1]); upk(v23, V[2][3][0], V[2][3][1]);
    float cnt[2]; upk(CNT, cnt[0], cnt[1]);
    float cx[2] = {cxA, cxB}, cy[2] = {cyA, cyB}, cz[2] = {czA, czB};

    float nxo[2], nyo[2], nzo[2], mo[2];
    #pragma unroll
    for (int l = 0; l < 2; ++l) {
        float e = dg[l][0], nx = V[0][0][l], ny = V[1][0][l], nz = V[2][0][l];
        if (dg[l][1] < e) { e = dg[l][1]; nx = V[0][1][l]; ny = V[1][1][l]; nz = V[2][1][l]; }
        if (dg[l][2] < e) { e = dg[l][2]; nx = V[0][2][l]; ny = V[1][2][l]; nz = V[2][2][l]; }
        if (dg[l][3] < e) { e = dg[l][3]; nx = V[0][3][l]; ny = V[1][3][l]; nz = V[2][3][l]; }

        float n2  = fmaf(nx, nx, fmaf(ny, ny, nz * nz));
        float inv = rsqrt_approx(fmaxf(n2, 1e-24f));
        float dot = fmaf(nx, cx[l], fmaf(ny, cy[l], nz * cz[l]));
        float flip = (dot > 0.0f) ? 1.0f : ((dot < 0.0f) ? -1.0f : 0.0f);
        float sgn = inv * flip;
        nx *= sgn; ny *= sgn; nz *= sgn;

        float fn2 = fmaf(nx, nx, fmaf(ny, ny, nz * nz));
        bool cv = (fabsf(cz[l] - 5.0f) < 5.0f);
        bool m = cv && (cnt[l] >= 4.0f) && (fn2 > 0.25f);
        nxo[l] = nx; nyo[l] = ny; nzo[l] = nz; mo[l] = m ? 1.0f : 0.0f;
    }

    // off is even -> 8B-aligned float2 stores
    *(float2*)(out + (size_t)(b * 3 + 0) * HW + off) = make_float2(nxo[0], nxo[1]);
    *(float2*)(out + (size_t)(b * 3 + 1) * HW + off) = make_float2(nyo[0], nyo[1]);
    *(float2*)(out + (size_t)(b * 3 + 2) * HW + off) = make_float2(nzo[0], nzo[1]);
    *(float2*)(out + (size_t)(B * 3 + b) * HW + off) = make_float2(mo[0], mo[1]);
}

extern "C" void kernel_launch(void* const* d_in, const int* in_sizes, int n_in,
                              void* d_out, int out_size) {
    const float* pts = (const float*)d_in[0];
    float* out = (float*)d_out;
    int B = in_sizes[0] / (3 * KH * KW);
    dim3 block(BX, 1, 1);
    dim3 grid(KW / (2 * BX), KH, B);   // 5 x 480 x B
    d2n_kernel<<<grid, block>>>(pts, out, B);
}